// round 10
// baseline (speedup 1.0000x reference)
#include <cuda_runtime.h>
#include <stdint.h>
#include <stddef.h>

#define T_TOK 4096
#define HDIM  1024
#define FDIM  2048
#define NEXP  8

// ---------------- scratch (__device__ globals: alloc-free) ----------------
__device__ int   g_cnt[NEXP];
__device__ int   g_tok[NEXP * T_TOK];
__device__ float g_wt [NEXP * T_TOK];
__device__ float g_h  [(size_t)NEXP * T_TOK * FDIM];   // silu(XW1)*XW3, tf32, k-perm
__device__ float g_xr [(size_t)T_TOK * HDIM];          // x tf32-rounded, k-perm
__device__ float g_w1t[(size_t)NEXP * FDIM * HDIM];    // w1^T [E][F][H], k-perm
__device__ float g_w3t[(size_t)NEXP * FDIM * HDIM];    // w3^T [E][F][H], k-perm
__device__ float g_w2t[(size_t)NEXP * HDIM * FDIM];    // w2^T [E][H][F], k-perm

// ---------------- helpers ----------------
__device__ __forceinline__ uint32_t smem_u32(const void* p) {
    uint32_t a;
    asm("{ .reg .u64 t; cvta.to.shared.u64 t, %1; cvt.u32.u64 %0, t; }" : "=r"(a) : "l"(p));
    return a;
}
__device__ __forceinline__ float rna_tf32(float f) {
    uint32_t r;
    asm("cvt.rna.tf32.f32 %0, %1;" : "=r"(r) : "f"(f));
    return __uint_as_float(r);
}
// logical k -> physical k within 16-blocks: phys = 4*(k%4) + k/4
__device__ __forceinline__ int perm16(int f) {
    return (f & ~15) | ((f & 3) << 2) | ((f >> 2) & 3);
}
// smem offset: row stride 128B (32 floats), 8 chunks of 16B, xor-swizzled
__device__ __forceinline__ uint32_t swoff(int row, int chunk) {
    return (uint32_t)(row * 128 + ((chunk ^ ((row & 1) << 2)) << 4));
}

#define CP_ASYNC16(dst, src) \
    asm volatile("cp.async.cg.shared.global [%0], [%1], 16;\n" :: "r"(dst), "l"(src))
#define CP_COMMIT() asm volatile("cp.async.commit_group;\n")
#define CP_WAIT0()  asm volatile("cp.async.wait_group 0;\n")

__device__ __forceinline__ void lds128(uint4& v, uint32_t addr) {
    asm volatile("ld.shared.v4.b32 {%0,%1,%2,%3}, [%4];"
                 : "=r"(v.x), "=r"(v.y), "=r"(v.z), "=r"(v.w) : "r"(addr));
}
__device__ __forceinline__ void mma8(float* d, uint32_t a0, uint32_t a1, uint32_t a2,
                                     uint32_t a3, uint32_t b0, uint32_t b1) {
    asm volatile(
        "mma.sync.aligned.m16n8k8.row.col.f32.tf32.tf32.f32 "
        "{%0,%1,%2,%3}, {%4,%5,%6,%7}, {%8,%9}, {%0,%1,%2,%3};\n"
        : "+f"(d[0]), "+f"(d[1]), "+f"(d[2]), "+f"(d[3])
        : "r"(a0), "r"(a1), "r"(a2), "r"(a3), "r"(b0), "r"(b1));
}

// ---------------- init ----------------
__global__ void init_counts() {
    if (threadIdx.x < NEXP) g_cnt[threadIdx.x] = 0;
}

// ---------------- router ----------------
__global__ void router_kernel(const float* __restrict__ x,
                              const float* __restrict__ gw,
                              float* __restrict__ logits_out,
                              int write_logits)
{
    int tok  = (blockIdx.x * blockDim.x + threadIdx.x) >> 5;
    int lane = threadIdx.x & 31;
    if (tok >= T_TOK) return;
    const float* xr = x + (size_t)tok * HDIM;

    float acc[NEXP];
#pragma unroll
    for (int e = 0; e < NEXP; e++) acc[e] = 0.f;
    for (int h = lane; h < HDIM; h += 32) {
        float xv = xr[h];
#pragma unroll
        for (int e = 0; e < NEXP; e++) acc[e] = fmaf(xv, gw[e * HDIM + h], acc[e]);
    }
#pragma unroll
    for (int e = 0; e < NEXP; e++) {
#pragma unroll
        for (int off = 16; off > 0; off >>= 1)
            acc[e] += __shfl_xor_sync(0xffffffffu, acc[e], off);
    }
    if (lane == 0) {
        if (write_logits) {
#pragma unroll
            for (int e = 0; e < NEXP; e++) logits_out[tok * NEXP + e] = acc[e];
        }
        float mx = acc[0];
#pragma unroll
        for (int e = 1; e < NEXP; e++) mx = fmaxf(mx, acc[e]);
        float p[NEXP], s = 0.f;
#pragma unroll
        for (int e = 0; e < NEXP; e++) { p[e] = __expf(acc[e] - mx); s += p[e]; }
        float inv = 1.f / s;
#pragma unroll
        for (int e = 0; e < NEXP; e++) p[e] *= inv;

        int i1 = 0; float m1 = p[0];
#pragma unroll
        for (int e = 1; e < NEXP; e++) if (p[e] > m1) { m1 = p[e]; i1 = e; }
        int i2 = -1; float m2 = -1.f;
#pragma unroll
        for (int e = 0; e < NEXP; e++) {
            if (e == i1) continue;
            if (p[e] > m2) { m2 = p[e]; i2 = e; }
        }
        int pos1 = atomicAdd(&g_cnt[i1], 1);
        g_tok[i1 * T_TOK + pos1] = tok;  g_wt[i1 * T_TOK + pos1] = m1;
        int pos2 = atomicAdd(&g_cnt[i2], 1);
        g_tok[i2 * T_TOK + pos2] = tok;  g_wt[i2 * T_TOK + pos2] = m2;
    }
}

// ---------------- pre-pass: round x to tf32 + k-permute (float4 out) ------
__global__ void round_x_perm(const float* __restrict__ in) {
    int p = (blockIdx.x * 256 + threadIdx.x) * 4;      // phys base
    int grp = p & ~15, j = (p >> 2) & 3;
    float4 o;
    o.x = rna_tf32(in[grp + j]);
    o.y = rna_tf32(in[grp + 4 + j]);
    o.z = rna_tf32(in[grp + 8 + j]);
    o.w = rna_tf32(in[grp + 12 + j]);
    *(float4*)(g_xr + p) = o;
}

// ---------------- pre-pass: round + transpose + k-perm weights ------------
// in: [E][K][N] -> out: [E][N][K] (K phys-permuted per 16), tf32-rounded
// DUAL=1: blockIdx.z in [0,16): z<8 -> w1->g_w1t, z>=8 -> w3->g_w3t
template<int DUAL, int K, int N>
__global__ void round_transpose_kernel(const float* __restrict__ inA,
                                       const float* __restrict__ inB) {
    __shared__ float t[32][33];
    int ez = blockIdx.z;
    const float* in;
    float* out;
    if (DUAL) {
        int e = ez & 7;
        in  = ((ez < 8) ? inA : inB) + (size_t)e * K * N;
        out = ((ez < 8) ? g_w1t : g_w3t) + (size_t)e * K * N;
    } else {
        in  = inA + (size_t)ez * K * N;
        out = g_w2t + (size_t)ez * K * N;
    }
    int n0 = blockIdx.x * 32, k0 = blockIdx.y * 32;

    int kr = threadIdx.x >> 3;            // 0..31
    int nc = (threadIdx.x & 7) * 4;
    float4 v = *(const float4*)(in + (size_t)(k0 + kr) * N + n0 + nc);
    t[kr][nc] = v.x; t[kr][nc + 1] = v.y; t[kr][nc + 2] = v.z; t[kr][nc + 3] = v.w;
    __syncthreads();

    int nr = threadIdx.x >> 3;            // 0..31 (n within tile)
    int c  = threadIdx.x & 7;             // phys 16B chunk
    int g  = (c >> 2) * 16, j = c & 3;    // phys base = g + 4j
    float4 o;
    o.x = rna_tf32(t[g + j     ][nr]);
    o.y = rna_tf32(t[g + 4 + j ][nr]);
    o.z = rna_tf32(t[g + 8 + j ][nr]);
    o.w = rna_tf32(t[g + 12 + j][nr]);
    *(float4*)(out + (size_t)(n0 + nr) * K + k0 + g + 4 * j) = o;
}

// =====================================================================
// GEMM13 fused: h = silu(Xg @ W1) * (Xg @ W3)
// BM=256, BN=64, BK=32, 512 thr (16 warps 8m x 2n). Warp: 32r x 32c x 2 mats.
// smem/stage (48KB): A[0,32K) B1[32K,40K) B3[40K,48K). 2 stages, wait0.
// 1 CTA/SM. Halves B L2-traffic per flop vs BM=128.
// =====================================================================
__global__ void __launch_bounds__(512, 1)
moe_gemm13()
{
    const int e   = blockIdx.z;
    const int cnt = g_cnt[e];
    const int m0  = blockIdx.x * 256;
    if (m0 >= cnt) return;
    const int n0  = blockIdx.y * 64;

    extern __shared__ char dsm[];
    const uint32_t sb = (smem_u32(dsm) + 127u) & ~127u;
    __shared__ const float* s_arow[256];

    const int tid  = threadIdx.x;
    const int warp = tid >> 5;
    const int lane = tid & 31;
    const int qr   = lane >> 2;
    const int qc   = lane & 3;
    const int rq   = warp & 7;       // 8 warps in M
    const int cf   = warp >> 3;      // 2 warps in N

    if (tid < 256) {
        int mm = min(m0 + tid, cnt - 1);
        s_arow[tid] = g_xr + (size_t)g_tok[e * T_TOK + mm] * HDIM;
    }
    __syncthreads();

    const float* b1b = g_w1t + (size_t)e * FDIM * HDIM + (size_t)n0 * HDIM;
    const float* b3b = g_w3t + (size_t)e * FDIM * HDIM + (size_t)n0 * HDIM;

    const int ch  = tid & 7;
    const int rr  = tid >> 3;       // 0..63
    const float* pA[4]; uint32_t dA[4];
#pragma unroll
    for (int i = 0; i < 4; i++) {
        int row = i * 64 + rr;       // 0..255
        pA[i] = s_arow[row] + ch * 4;
        dA[i] = sb + swoff(row, ch);
    }
    const float* pB1 = b1b + (size_t)rr * HDIM + ch * 4;   // rows 0..63
    const float* pB3 = b3b + (size_t)rr * HDIM + ch * 4;
    const uint32_t dB = sb + 32768u + swoff(rr, ch);

#define LOAD13(st_, k0_) do {                                             \
    uint32_t so_ = (uint32_t)(st_) * 49152u;                              \
    _Pragma("unroll")                                                     \
    for (int i_ = 0; i_ < 4; i_++)                                        \
        CP_ASYNC16(dA[i_] + so_, pA[i_] + (k0_));                         \
    CP_ASYNC16(dB + so_,         pB1 + (k0_));                            \
    CP_ASYNC16(dB + 8192u + so_, pB3 + (k0_));                            \
    CP_COMMIT();                                                          \
} while (0)

    float acc1[2][4][4], acc3[2][4][4];
#pragma unroll
    for (int mt = 0; mt < 2; mt++)
#pragma unroll
        for (int nt = 0; nt < 4; nt++)
#pragma unroll
            for (int i = 0; i < 4; i++) { acc1[mt][nt][i] = 0.f; acc3[mt][nt][i] = 0.f; }

    LOAD13(0, 0);
    const int NT = HDIM / 32;   // 32
    for (int t = 0; t < NT; t++) {
        const uint32_t st = (uint32_t)(t & 1) * 49152u;
        CP_WAIT0();
        __syncthreads();
        if (t + 1 < NT) LOAD13((t + 1) & 1, (t + 1) * 32);

#pragma unroll
        for (int s = 0; s < 2; s++) {
            uint4 alo[2], ahi[2];
#pragma unroll
            for (int mt = 0; mt < 2; mt++) {
                int r = rq * 32 + mt * 16 + qr;
                lds128(alo[mt], sb + st + swoff(r,     4 * s + qc));
                lds128(ahi[mt], sb + st + swoff(r + 8, 4 * s + qc));
            }
#pragma unroll
            for (int nt = 0; nt < 4; nt++) {
                int n = cf * 32 + nt * 8 + qr;
                uint4 b1v, b3v;
                lds128(b1v, sb + st + 32768u + swoff(n, 4 * s + qc));
                lds128(b3v, sb + st + 40960u + swoff(n, 4 * s + qc));
#pragma unroll
                for (int mt = 0; mt < 2; mt++) {
                    mma8(acc1[mt][nt], alo[mt].x, ahi[mt].x, alo[mt].y, ahi[mt].y, b1v.x, b1v.y);
                    mma8(acc1[mt][nt], alo[mt].z, ahi[mt].z, alo[mt].w, ahi[mt].w, b1v.z, b1v.w);
                    mma8(acc3[mt][nt], alo[mt].x, ahi[mt].x, alo[mt].y, ahi[mt].y, b3v.x, b3v.y);
                    mma8(acc3[mt][nt], alo[mt].z, ahi[mt].z, alo[mt].w, ahi[mt].w, b3v.z, b3v.w);
                }
            }
        }
    }

    // epilogue: g_h[m][perm16(f)] = rna(silu(d1)*d3)
#pragma unroll
    for (int mt = 0; mt < 2; mt++) {
#pragma unroll
        for (int h = 0; h < 2; h++) {
            int m = m0 + rq * 32 + mt * 16 + qr + 8 * h;
            if (m >= cnt) continue;
            float* hrow = g_h + ((size_t)e * T_TOK + m) * FDIM;
#pragma unroll
            for (int nt = 0; nt < 4; nt++) {
#pragma unroll
                for (int b = 0; b < 2; b++) {
                    float d1 = acc1[mt][nt][2 * h + b];
                    float d3 = acc3[mt][nt][2 * h + b];
                    float v = rna_tf32(d1 / (1.f + __expf(-d1)) * d3);
                    int f = n0 + cf * 32 + nt * 8 + qc * 2 + b;
                    hrow[perm16(f)] = v;
                }
            }
        }
    }
#undef LOAD13
}

// =====================================================================
// GEMM2: y += wt * (h @ W2).  BM=256, BN=128, BK=32, 512 thr (8m x 2n warps).
// Warp: 32r x 64c. smem/stage (48KB): A[0,32K) B[32K,48K). 2 stages, wait0.
// =====================================================================
__global__ void __launch_bounds__(512, 1)
moe_gemm2(float* __restrict__ y)
{
    const int e   = blockIdx.z;
    const int cnt = g_cnt[e];
    const int m0  = blockIdx.x * 256;
    if (m0 >= cnt) return;
    const int n0  = blockIdx.y * 128;

    extern __shared__ char dsm[];
    const uint32_t sb = (smem_u32(dsm) + 127u) & ~127u;
    __shared__ const float* s_arow[256];

    const int tid  = threadIdx.x;
    const int warp = tid >> 5;
    const int lane = tid & 31;
    const int qr   = lane >> 2;
    const int qc   = lane & 3;
    const int rq   = warp & 7;
    const int cf   = warp >> 3;

    if (tid < 256) {
        int mm = min(m0 + tid, cnt - 1);
        s_arow[tid] = g_h + ((size_t)e * T_TOK + mm) * FDIM;
    }
    __syncthreads();

    const float* bb = g_w2t + (size_t)e * HDIM * FDIM + (size_t)n0 * FDIM;

    const int ch = tid & 7;
    const int rr = tid >> 3;        // 0..63
    const float* pA[4]; uint32_t dA[4];
#pragma unroll
    for (int i = 0; i < 4; i++) {
        int row = i * 64 + rr;
        pA[i] = s_arow[row] + ch * 4;
        dA[i] = sb + swoff(row, ch);
    }
    const float* pB[2]; uint32_t dB[2];
#pragma unroll
    for (int i = 0; i < 2; i++) {
        int row = i * 64 + rr;      // 0..127
        pB[i] = bb + (size_t)row * FDIM + ch * 4;
        dB[i] = sb + 32768u + swoff(row, ch);
    }

#define LOAD2(st_, k0_) do {                                              \
    uint32_t so_ = (uint32_t)(st_) * 49152u;                              \
    _Pragma("unroll")                                                     \
    for (int i_ = 0; i_ < 4; i_++)                                        \
        CP_ASYNC16(dA[i_] + so_, pA[i_] + (k0_));                         \
    _Pragma("unroll")                                                     \
    for (int i_ = 0; i_ < 2; i_++)                                        \
        CP_ASYNC16(dB[i_] + so_, pB[i_] + (k0_));                         \
    CP_COMMIT();                                                          \
} while (0)

    float acc[2][8][4];
#pragma unroll
    for (int mt = 0; mt < 2; mt++)
#pragma unroll
        for (int nt = 0; nt < 8; nt++)
#pragma unroll
            for (int i = 0; i < 4; i++) acc[mt][nt][i] = 0.f;

    LOAD2(0, 0);
    const int NT = FDIM / 32;   // 64
    for (int t = 0; t < NT; t++) {
        const uint32_t st = (uint32_t)(t & 1) * 49152u;
        CP_WAIT0();
        __syncthreads();
        if (t + 1 < NT) LOAD2((t + 1) & 1, (t + 1) * 32);

#pragma unroll
        for (int s = 0; s < 2; s++) {
            uint4 alo[2], ahi[2];
#pragma unroll
            for (int mt = 0; mt < 2; mt++) {
                int r = rq * 32 + mt * 16 + qr;
                lds128(alo[mt], sb + st + swoff(r,     4 * s + qc));
                lds128(ahi[mt], sb + st + swoff(r + 8, 4 * s + qc));
            }
#pragma unroll
            for (int nt = 0; nt < 8; nt++) {
                int n = cf * 64 + nt * 8 + qr;
                uint4 bv;
                lds128(bv, sb + st + 32768u + swoff(n, 4 * s + qc));
#pragma unroll
                for (int mt = 0; mt < 2; mt++) {
                    mma8(acc[mt][nt], alo[mt].x, ahi[mt].x, alo[mt].y, ahi[mt].y, bv.x, bv.y);
                    mma8(acc[mt][nt], alo[mt].z, ahi[mt].z, alo[mt].w, ahi[mt].w, bv.z, bv.w);
                }
            }
        }
    }

    // epilogue: y[tok] += wt * D (REDG atomics - measured cheap)
#pragma unroll
    for (int mt = 0; mt < 2; mt++) {
#pragma unroll
        for (int h = 0; h < 2; h++) {
            int m = m0 + rq * 32 + mt * 16 + qr + 8 * h;
            if (m >= cnt) continue;
            float w   = g_wt [e * T_TOK + m];
            int   tok = g_tok[e * T_TOK + m];
            float* yrow = y + (size_t)tok * HDIM + n0 + cf * 64;
#pragma unroll
            for (int nt = 0; nt < 8; nt++) {
#pragma unroll
                for (int b = 0; b < 2; b++)
                    atomicAdd(yrow + nt * 8 + qc * 2 + b, w * acc[mt][nt][2 * h + b]);
            }
        }
    }
#undef LOAD2
}

// ---------------- launch ----------------
extern "C" void kernel_launch(void* const* d_in, const int* in_sizes, int n_in,
                              void* d_out, int out_size)
{
    const float* x  = (const float*)d_in[0];   // [2,2048,1024]
    const float* gw = (const float*)d_in[1];   // [8,1024]
    const float* w1 = (const float*)d_in[2];   // [8,1024,2048]
    const float* w3 = (const float*)d_in[3];   // [8,1024,2048]
    const float* w2 = (const float*)d_in[4];   // [8,2048,1024]
    float* out = (float*)d_out;

    const int SMEM = 2 * 49152 + 128;   // 98432
    cudaFuncSetAttribute(moe_gemm13, cudaFuncAttributeMaxDynamicSharedMemorySize, SMEM);
    cudaFuncSetAttribute(moe_gemm2,  cudaFuncAttributeMaxDynamicSharedMemorySize, SMEM);

    cudaMemsetAsync(out, 0, (size_t)T_TOK * HDIM * sizeof(float));
    init_counts<<<1, 32>>>();

    int write_logits = (out_size >= T_TOK * HDIM + T_TOK * NEXP) ? 1 : 0;
    router_kernel<<<T_TOK / 4, 128>>>(x, gw, out + (size_t)T_TOK * HDIM, write_logits);

    round_x_perm<<<T_TOK * HDIM / 1024, 256>>>(x);
    {
        dim3 b(256);
        round_transpose_kernel<1, HDIM, FDIM>
            <<<dim3(FDIM / 32, HDIM / 32, 2 * NEXP), b>>>(w1, w3);
        round_transpose_kernel<0, FDIM, HDIM>
            <<<dim3(HDIM / 32, FDIM / 32, NEXP), b>>>(w2, nullptr);
    }

    // grid.x = M-blocks fastest (B-tile / expert A-slice L2 reuse)
    moe_gemm13<<<dim3(T_TOK / 256, FDIM / 64, NEXP), 512, SMEM>>>();
    moe_gemm2 <<<dim3(T_TOK / 256, HDIM / 128, NEXP), 512, SMEM>>>(out);
}

// round 11
// speedup vs baseline: 1.1172x; 1.1172x over previous
#include <cuda_runtime.h>
#include <stdint.h>
#include <stddef.h>

#define T_TOK 4096
#define HDIM  1024
#define FDIM  2048
#define NEXP  8

// ---------------- scratch (__device__ globals: alloc-free) ----------------
__device__ int   g_cnt[NEXP];
__device__ int   g_tok[NEXP * T_TOK];
__device__ float g_wt [NEXP * T_TOK];
__device__ float g_h  [(size_t)NEXP * T_TOK * FDIM];   // silu(XW1)*XW3, tf32, k-perm
__device__ float g_xr [(size_t)T_TOK * HDIM];          // x tf32-rounded, k-perm
__device__ float g_w1t[(size_t)NEXP * FDIM * HDIM];    // w1^T [E][F][H], k-perm
__device__ float g_w3t[(size_t)NEXP * FDIM * HDIM];    // w3^T [E][F][H], k-perm
__device__ float g_w2t[(size_t)NEXP * HDIM * FDIM];    // w2^T [E][H][F], k-perm

// ---------------- helpers ----------------
__device__ __forceinline__ uint32_t smem_u32(const void* p) {
    uint32_t a;
    asm("{ .reg .u64 t; cvta.to.shared.u64 t, %1; cvt.u32.u64 %0, t; }" : "=r"(a) : "l"(p));
    return a;
}
__device__ __forceinline__ float rna_tf32(float f) {
    uint32_t r;
    asm("cvt.rna.tf32.f32 %0, %1;" : "=r"(r) : "f"(f));
    return __uint_as_float(r);
}
// logical k -> physical k within 16-blocks: phys = 4*(k%4) + k/4
__device__ __forceinline__ int perm16(int f) {
    return (f & ~15) | ((f & 3) << 2) | ((f >> 2) & 3);
}
// smem offset: row stride 128B (32 floats), 8 chunks of 16B, xor-swizzled
__device__ __forceinline__ uint32_t swoff(int row, int chunk) {
    return (uint32_t)(row * 128 + ((chunk ^ ((row & 1) << 2)) << 4));
}

#define CP_ASYNC16(dst, src) \
    asm volatile("cp.async.cg.shared.global [%0], [%1], 16;\n" :: "r"(dst), "l"(src))
#define CP_COMMIT() asm volatile("cp.async.commit_group;\n")
#define CP_WAIT0()  asm volatile("cp.async.wait_group 0;\n")

__device__ __forceinline__ void lds128(uint4& v, uint32_t addr) {
    asm volatile("ld.shared.v4.b32 {%0,%1,%2,%3}, [%4];"
                 : "=r"(v.x), "=r"(v.y), "=r"(v.z), "=r"(v.w) : "r"(addr));
}
__device__ __forceinline__ void mma8(float* d, uint32_t a0, uint32_t a1, uint32_t a2,
                                     uint32_t a3, uint32_t b0, uint32_t b1) {
    asm volatile(
        "mma.sync.aligned.m16n8k8.row.col.f32.tf32.tf32.f32 "
        "{%0,%1,%2,%3}, {%4,%5,%6,%7}, {%8,%9}, {%0,%1,%2,%3};\n"
        : "+f"(d[0]), "+f"(d[1]), "+f"(d[2]), "+f"(d[3])
        : "r"(a0), "r"(a1), "r"(a2), "r"(a3), "r"(b0), "r"(b1));
}

// ---------------- init ----------------
__global__ void init_counts() {
    if (threadIdx.x < NEXP) g_cnt[threadIdx.x] = 0;
}

// ---------------- router ----------------
__global__ void router_kernel(const float* __restrict__ x,
                              const float* __restrict__ gw,
                              float* __restrict__ logits_out,
                              int write_logits)
{
    int tok  = (blockIdx.x * blockDim.x + threadIdx.x) >> 5;
    int lane = threadIdx.x & 31;
    if (tok >= T_TOK) return;
    const float* xr = x + (size_t)tok * HDIM;

    float acc[NEXP];
#pragma unroll
    for (int e = 0; e < NEXP; e++) acc[e] = 0.f;
    for (int h = lane; h < HDIM; h += 32) {
        float xv = xr[h];
#pragma unroll
        for (int e = 0; e < NEXP; e++) acc[e] = fmaf(xv, gw[e * HDIM + h], acc[e]);
    }
#pragma unroll
    for (int e = 0; e < NEXP; e++) {
#pragma unroll
        for (int off = 16; off > 0; off >>= 1)
            acc[e] += __shfl_xor_sync(0xffffffffu, acc[e], off);
    }
    if (lane == 0) {
        if (write_logits) {
#pragma unroll
            for (int e = 0; e < NEXP; e++) logits_out[tok * NEXP + e] = acc[e];
        }
        float mx = acc[0];
#pragma unroll
        for (int e = 1; e < NEXP; e++) mx = fmaxf(mx, acc[e]);
        float p[NEXP], s = 0.f;
#pragma unroll
        for (int e = 0; e < NEXP; e++) { p[e] = __expf(acc[e] - mx); s += p[e]; }
        float inv = 1.f / s;
#pragma unroll
        for (int e = 0; e < NEXP; e++) p[e] *= inv;

        int i1 = 0; float m1 = p[0];
#pragma unroll
        for (int e = 1; e < NEXP; e++) if (p[e] > m1) { m1 = p[e]; i1 = e; }
        int i2 = -1; float m2 = -1.f;
#pragma unroll
        for (int e = 0; e < NEXP; e++) {
            if (e == i1) continue;
            if (p[e] > m2) { m2 = p[e]; i2 = e; }
        }
        int pos1 = atomicAdd(&g_cnt[i1], 1);
        g_tok[i1 * T_TOK + pos1] = tok;  g_wt[i1 * T_TOK + pos1] = m1;
        int pos2 = atomicAdd(&g_cnt[i2], 1);
        g_tok[i2 * T_TOK + pos2] = tok;  g_wt[i2 * T_TOK + pos2] = m2;
    }
}

// ---------------- fused pre-pass: all transposes + x rounding -------------
// grid (64, 32, 25), block 256.
//   z in [0,8)  : w1 expert z  -> g_w1t   (K=1024, N=2048)
//   z in [8,16) : w3 expert z-8-> g_w3t   (K=1024, N=2048)
//   z in [16,24): w2 expert z-16->g_w2t   (K=2048, N=1024; bx/by roles swapped)
//   z == 24     : x tf32-round + k-perm -> g_xr (8 floats/thread)
__global__ void prepass_kernel(const float* __restrict__ x,
                               const float* __restrict__ w1,
                               const float* __restrict__ w3,
                               const float* __restrict__ w2)
{
    const int z = blockIdx.z;
    if (z == 24) {
        int base = ((blockIdx.y * 64 + blockIdx.x) * 256 + threadIdx.x) * 8;
#pragma unroll
        for (int q = 0; q < 2; q++) {
            int p = base + q * 4;                  // phys base, 4-aligned
            int grp = p & ~15, j = (p >> 2) & 3;
            float4 o;
            o.x = rna_tf32(x[grp + j]);
            o.y = rna_tf32(x[grp + 4 + j]);
            o.z = rna_tf32(x[grp + 8 + j]);
            o.w = rna_tf32(x[grp + 12 + j]);
            *(float4*)(g_xr + p) = o;
        }
        return;
    }

    __shared__ float t[32][33];
    const float* in;
    float* out;
    int K, N, n0, k0;
    if (z < 16) {
        K = HDIM; N = FDIM;
        int e = z & 7;
        in  = ((z < 8) ? w1 : w3) + (size_t)e * K * N;
        out = ((z < 8) ? g_w1t : g_w3t) + (size_t)e * K * N;
        n0 = blockIdx.x * 32; k0 = blockIdx.y * 32;
    } else {
        K = FDIM; N = HDIM;
        int e = z - 16;
        in  = w2 + (size_t)e * K * N;
        out = g_w2t + (size_t)e * K * N;
        n0 = blockIdx.y * 32; k0 = blockIdx.x * 32;
    }

    int kr = threadIdx.x >> 3;            // 0..31
    int nc = (threadIdx.x & 7) * 4;
    float4 v = *(const float4*)(in + (size_t)(k0 + kr) * N + n0 + nc);
    t[kr][nc] = v.x; t[kr][nc + 1] = v.y; t[kr][nc + 2] = v.z; t[kr][nc + 3] = v.w;
    __syncthreads();

    int nr = threadIdx.x >> 3;            // 0..31 (n within tile)
    int c  = threadIdx.x & 7;             // phys 16B chunk
    int g  = (c >> 2) * 16, j = c & 3;    // phys base = g + 4j
    float4 o;
    o.x = rna_tf32(t[g + j     ][nr]);
    o.y = rna_tf32(t[g + 4 + j ][nr]);
    o.z = rna_tf32(t[g + 8 + j ][nr]);
    o.w = rna_tf32(t[g + 12 + j][nr]);
    *(float4*)(out + (size_t)(n0 + nr) * K + k0 + g + 4 * j) = o;
}

// =====================================================================
// GEMM13 fused: h = silu(Xg @ W1) * (Xg @ W3)    [exact R3 config, 760us]
// BM=128, BN=64, BK=32, 256 thr (8 warps 4m x 2n). Warp: 32r x 32c x 2 mats.
// smem/stage (32KB): A[0,16K) B1[16K,24K) B3[24K,32K). 2 stages, wait0.
// =====================================================================
__global__ void __launch_bounds__(256, 2)
moe_gemm13()
{
    const int e   = blockIdx.z;
    const int cnt = g_cnt[e];
    const int m0  = blockIdx.x * 128;
    if (m0 >= cnt) return;
    const int n0  = blockIdx.y * 64;

    extern __shared__ char dsm[];
    const uint32_t sb = (smem_u32(dsm) + 127u) & ~127u;
    __shared__ const float* s_arow[128];

    const int tid  = threadIdx.x;
    const int warp = tid >> 5;
    const int lane = tid & 31;
    const int qr   = lane >> 2;
    const int qc   = lane & 3;
    const int rq   = warp & 3;
    const int cf   = warp >> 2;

    if (tid < 128) {
        int mm = min(m0 + tid, cnt - 1);
        s_arow[tid] = g_xr + (size_t)g_tok[e * T_TOK + mm] * HDIM;
    }
    __syncthreads();

    const float* b1b = g_w1t + (size_t)e * FDIM * HDIM + (size_t)n0 * HDIM;
    const float* b3b = g_w3t + (size_t)e * FDIM * HDIM + (size_t)n0 * HDIM;

    const int ch  = tid & 7;
    const int rr  = tid >> 3;       // 0..31
    const float* pA[4]; uint32_t dA[4];
#pragma unroll
    for (int i = 0; i < 4; i++) {
        int row = i * 32 + rr;
        pA[i] = s_arow[row] + ch * 4;
        dA[i] = sb + swoff(row, ch);
    }
    const float* pB1[2]; const float* pB3[2]; uint32_t dB[2];
#pragma unroll
    for (int i = 0; i < 2; i++) {
        int row = i * 32 + rr;      // 0..63
        pB1[i] = b1b + (size_t)row * HDIM + ch * 4;
        pB3[i] = b3b + (size_t)row * HDIM + ch * 4;
        dB[i]  = sb + 16384u + swoff(row, ch);
    }

#define LOAD13(st_, k0_) do {                                             \
    uint32_t so_ = (uint32_t)(st_) * 32768u;                              \
    _Pragma("unroll")                                                     \
    for (int i_ = 0; i_ < 4; i_++)                                        \
        CP_ASYNC16(dA[i_] + so_, pA[i_] + (k0_));                         \
    _Pragma("unroll")                                                     \
    for (int i_ = 0; i_ < 2; i_++) {                                      \
        CP_ASYNC16(dB[i_] + so_,         pB1[i_] + (k0_));                \
        CP_ASYNC16(dB[i_] + 8192u + so_, pB3[i_] + (k0_));                \
    }                                                                     \
    CP_COMMIT();                                                          \
} while (0)

    float acc1[2][4][4], acc3[2][4][4];
#pragma unroll
    for (int mt = 0; mt < 2; mt++)
#pragma unroll
        for (int nt = 0; nt < 4; nt++)
#pragma unroll
            for (int i = 0; i < 4; i++) { acc1[mt][nt][i] = 0.f; acc3[mt][nt][i] = 0.f; }

    LOAD13(0, 0);
    const int NT = HDIM / 32;   // 32
    for (int t = 0; t < NT; t++) {
        const uint32_t st = (uint32_t)(t & 1) * 32768u;
        CP_WAIT0();
        __syncthreads();
        if (t + 1 < NT) LOAD13((t + 1) & 1, (t + 1) * 32);

#pragma unroll
        for (int s = 0; s < 2; s++) {
            uint4 alo[2], ahi[2];
#pragma unroll
            for (int mt = 0; mt < 2; mt++) {
                int r = rq * 32 + mt * 16 + qr;
                lds128(alo[mt], sb + st + swoff(r,     4 * s + qc));
                lds128(ahi[mt], sb + st + swoff(r + 8, 4 * s + qc));
            }
#pragma unroll
            for (int nt = 0; nt < 4; nt++) {
                int n = cf * 32 + nt * 8 + qr;
                uint4 b1v, b3v;
                lds128(b1v, sb + st + 16384u + swoff(n, 4 * s + qc));
                lds128(b3v, sb + st + 24576u + swoff(n, 4 * s + qc));
#pragma unroll
                for (int mt = 0; mt < 2; mt++) {
                    mma8(acc1[mt][nt], alo[mt].x, ahi[mt].x, alo[mt].y, ahi[mt].y, b1v.x, b1v.y);
                    mma8(acc1[mt][nt], alo[mt].z, ahi[mt].z, alo[mt].w, ahi[mt].w, b1v.z, b1v.w);
                    mma8(acc3[mt][nt], alo[mt].x, ahi[mt].x, alo[mt].y, ahi[mt].y, b3v.x, b3v.y);
                    mma8(acc3[mt][nt], alo[mt].z, ahi[mt].z, alo[mt].w, ahi[mt].w, b3v.z, b3v.w);
                }
            }
        }
    }

    // epilogue: g_h[m][perm16(f)] = rna(silu(d1)*d3)
#pragma unroll
    for (int mt = 0; mt < 2; mt++) {
#pragma unroll
        for (int h = 0; h < 2; h++) {
            int m = m0 + rq * 32 + mt * 16 + qr + 8 * h;
            if (m >= cnt) continue;
            float* hrow = g_h + ((size_t)e * T_TOK + m) * FDIM;
#pragma unroll
            for (int nt = 0; nt < 4; nt++) {
#pragma unroll
                for (int b = 0; b < 2; b++) {
                    float d1 = acc1[mt][nt][2 * h + b];
                    float d3 = acc3[mt][nt][2 * h + b];
                    float v = rna_tf32(d1 / (1.f + __expf(-d1)) * d3);
                    int f = n0 + cf * 32 + nt * 8 + qc * 2 + b;
                    hrow[perm16(f)] = v;
                }
            }
        }
    }
#undef LOAD13
}

// =====================================================================
// GEMM2: y += wt * (h @ W2).   [exact R3 config]
// BM=128, BN=128, BK=32, 256 thr. Warp: 32r x 64c.
// smem/stage (32KB): A[0,16K) B[16K,32K). 2 stages, wait0.
// =====================================================================
__global__ void __launch_bounds__(256, 2)
moe_gemm2(float* __restrict__ y)
{
    const int e   = blockIdx.z;
    const int cnt = g_cnt[e];
    const int m0  = blockIdx.x * 128;
    if (m0 >= cnt) return;
    const int n0  = blockIdx.y * 128;

    extern __shared__ char dsm[];
    const uint32_t sb = (smem_u32(dsm) + 127u) & ~127u;
    __shared__ const float* s_arow[128];

    const int tid  = threadIdx.x;
    const int warp = tid >> 5;
    const int lane = tid & 31;
    const int qr   = lane >> 2;
    const int qc   = lane & 3;
    const int rq   = warp & 3;
    const int cf   = warp >> 2;

    if (tid < 128) {
        int mm = min(m0 + tid, cnt - 1);
        s_arow[tid] = g_h + ((size_t)e * T_TOK + mm) * FDIM;
    }
    __syncthreads();

    const float* bb = g_w2t + (size_t)e * HDIM * FDIM + (size_t)n0 * FDIM;

    const int ch = tid & 7;
    const int rr = tid >> 3;
    const float* pA[4]; uint32_t dA[4]; const float* pB[4]; uint32_t dB[4];
#pragma unroll
    for (int i = 0; i < 4; i++) {
        int row = i * 32 + rr;
        pA[i] = s_arow[row] + ch * 4;
        dA[i] = sb + swoff(row, ch);
        pB[i] = bb + (size_t)row * FDIM + ch * 4;
        dB[i] = sb + 16384u + swoff(row, ch);
    }

#define LOAD2(st_, k0_) do {                                              \
    uint32_t so_ = (uint32_t)(st_) * 32768u;                              \
    _Pragma("unroll")                                                     \
    for (int i_ = 0; i_ < 4; i_++) {                                      \
        CP_ASYNC16(dA[i_] + so_, pA[i_] + (k0_));                         \
        CP_ASYNC16(dB[i_] + so_, pB[i_] + (k0_));                         \
    }                                                                     \
    CP_COMMIT();                                                          \
} while (0)

    float acc[2][8][4];
#pragma unroll
    for (int mt = 0; mt < 2; mt++)
#pragma unroll
        for (int nt = 0; nt < 8; nt++)
#pragma unroll
            for (int i = 0; i < 4; i++) acc[mt][nt][i] = 0.f;

    LOAD2(0, 0);
    const int NT = FDIM / 32;   // 64
    for (int t = 0; t < NT; t++) {
        const uint32_t st = (uint32_t)(t & 1) * 32768u;
        CP_WAIT0();
        __syncthreads();
        if (t + 1 < NT) LOAD2((t + 1) & 1, (t + 1) * 32);

#pragma unroll
        for (int s = 0; s < 2; s++) {
            uint4 alo[2], ahi[2];
#pragma unroll
            for (int mt = 0; mt < 2; mt++) {
                int r = rq * 32 + mt * 16 + qr;
                lds128(alo[mt], sb + st + swoff(r,     4 * s + qc));
                lds128(ahi[mt], sb + st + swoff(r + 8, 4 * s + qc));
            }
#pragma unroll
            for (int nt = 0; nt < 8; nt++) {
                int n = cf * 64 + nt * 8 + qr;
                uint4 bv;
                lds128(bv, sb + st + 16384u + swoff(n, 4 * s + qc));
#pragma unroll
                for (int mt = 0; mt < 2; mt++) {
                    mma8(acc[mt][nt], alo[mt].x, ahi[mt].x, alo[mt].y, ahi[mt].y, bv.x, bv.y);
                    mma8(acc[mt][nt], alo[mt].z, ahi[mt].z, alo[mt].w, ahi[mt].w, bv.z, bv.w);
                }
            }
        }
    }

    // epilogue: y[tok] += wt * D (REDG atomics - measured cheap)
#pragma unroll
    for (int mt = 0; mt < 2; mt++) {
#pragma unroll
        for (int h = 0; h < 2; h++) {
            int m = m0 + rq * 32 + mt * 16 + qr + 8 * h;
            if (m >= cnt) continue;
            float w   = g_wt [e * T_TOK + m];
            int   tok = g_tok[e * T_TOK + m];
            float* yrow = y + (size_t)tok * HDIM + n0 + cf * 64;
#pragma unroll
            for (int nt = 0; nt < 8; nt++) {
#pragma unroll
                for (int b = 0; b < 2; b++)
                    atomicAdd(yrow + nt * 8 + qc * 2 + b, w * acc[mt][nt][2 * h + b]);
            }
        }
    }
#undef LOAD2
}

// ---------------- launch ----------------
extern "C" void kernel_launch(void* const* d_in, const int* in_sizes, int n_in,
                              void* d_out, int out_size)
{
    const float* x  = (const float*)d_in[0];   // [2,2048,1024]
    const float* gw = (const float*)d_in[1];   // [8,1024]
    const float* w1 = (const float*)d_in[2];   // [8,1024,2048]
    const float* w3 = (const float*)d_in[3];   // [8,1024,2048]
    const float* w2 = (const float*)d_in[4];   // [8,2048,1024]
    float* out = (float*)d_out;

    const int SMEM = 2 * 32768 + 128;   // 65664
    cudaFuncSetAttribute(moe_gemm13, cudaFuncAttributeMaxDynamicSharedMemorySize, SMEM);
    cudaFuncSetAttribute(moe_gemm2,  cudaFuncAttributeMaxDynamicSharedMemorySize, SMEM);

    cudaMemsetAsync(out, 0, (size_t)T_TOK * HDIM * sizeof(float));
    init_counts<<<1, 32>>>();

    int write_logits = (out_size >= T_TOK * HDIM + T_TOK * NEXP) ? 1 : 0;
    router_kernel<<<T_TOK / 4, 128>>>(x, gw, out + (size_t)T_TOK * HDIM, write_logits);

    // ONE fused prepass launch (x round + w1/w3/w2 transpose)
    prepass_kernel<<<dim3(64, 32, 25), 256>>>(x, w1, w3, w2);

    // gemm13 now sits in the ncu -s 5 -c 1 capture window
    moe_gemm13<<<dim3(T_TOK / 128, FDIM / 64, NEXP), 256, SMEM>>>();
    moe_gemm2 <<<dim3(T_TOK / 128, HDIM / 128, NEXP), 256, SMEM>>>(out);
}

// round 12
// speedup vs baseline: 1.1618x; 1.0399x over previous
#include <cuda_runtime.h>
#include <stdint.h>
#include <stddef.h>

#define T_TOK 4096
#define HDIM  1024
#define FDIM  2048
#define NEXP  8

// ---------------- scratch (__device__ globals: alloc-free) ----------------
__device__ int   g_cnt[NEXP];
__device__ int   g_tok[NEXP * T_TOK];
__device__ float g_wt [NEXP * T_TOK];
__device__ float g_h  [(size_t)NEXP * T_TOK * FDIM];   // silu(XW1)*XW3, tf32, k-perm
__device__ float g_xr [(size_t)T_TOK * HDIM];          // x tf32-rounded, k-perm
__device__ float g_w1t[(size_t)NEXP * FDIM * HDIM];    // w1^T [E][F][H], k-perm
__device__ float g_w3t[(size_t)NEXP * FDIM * HDIM];    // w3^T [E][F][H], k-perm
__device__ float g_w2t[(size_t)NEXP * HDIM * FDIM];    // w2^T [E][H][F], k-perm

// ---------------- helpers ----------------
__device__ __forceinline__ uint32_t smem_u32(const void* p) {
    uint32_t a;
    asm("{ .reg .u64 t; cvta.to.shared.u64 t, %1; cvt.u32.u64 %0, t; }" : "=r"(a) : "l"(p));
    return a;
}
__device__ __forceinline__ float rna_tf32(float f) {
    uint32_t r;
    asm("cvt.rna.tf32.f32 %0, %1;" : "=r"(r) : "f"(f));
    return __uint_as_float(r);
}
// logical k -> physical k within 16-blocks: phys = 4*(k%4) + k/4
__device__ __forceinline__ int perm16(int f) {
    return (f & ~15) | ((f & 3) << 2) | ((f >> 2) & 3);
}
// smem offset: row stride 128B (32 floats), 8 chunks of 16B, xor-swizzled
__device__ __forceinline__ uint32_t swoff(int row, int chunk) {
    return (uint32_t)(row * 128 + ((chunk ^ ((row & 1) << 2)) << 4));
}

#define CP_ASYNC16(dst, src) \
    asm volatile("cp.async.cg.shared.global [%0], [%1], 16;\n" :: "r"(dst), "l"(src))
#define CP_COMMIT() asm volatile("cp.async.commit_group;\n")
#define CP_WAIT0()  asm volatile("cp.async.wait_group 0;\n")

__device__ __forceinline__ void lds128(uint4& v, uint32_t addr) {
    asm volatile("ld.shared.v4.b32 {%0,%1,%2,%3}, [%4];"
                 : "=r"(v.x), "=r"(v.y), "=r"(v.z), "=r"(v.w) : "r"(addr));
}
__device__ __forceinline__ void mma8(float* d, uint32_t a0, uint32_t a1, uint32_t a2,
                                     uint32_t a3, uint32_t b0, uint32_t b1) {
    asm volatile(
        "mma.sync.aligned.m16n8k8.row.col.f32.tf32.tf32.f32 "
        "{%0,%1,%2,%3}, {%4,%5,%6,%7}, {%8,%9}, {%0,%1,%2,%3};\n"
        : "+f"(d[0]), "+f"(d[1]), "+f"(d[2]), "+f"(d[3])
        : "r"(a0), "r"(a1), "r"(a2), "r"(a3), "r"(b0), "r"(b1));
}

// ---------------- init ----------------
__global__ void init_counts() {
    if (threadIdx.x < NEXP) g_cnt[threadIdx.x] = 0;
}

// ---------------- router ----------------
__global__ void router_kernel(const float* __restrict__ x,
                              const float* __restrict__ gw,
                              float* __restrict__ logits_out,
                              int write_logits)
{
    int tok  = (blockIdx.x * blockDim.x + threadIdx.x) >> 5;
    int lane = threadIdx.x & 31;
    if (tok >= T_TOK) return;
    const float* xr = x + (size_t)tok * HDIM;

    float acc[NEXP];
#pragma unroll
    for (int e = 0; e < NEXP; e++) acc[e] = 0.f;
    for (int h = lane; h < HDIM; h += 32) {
        float xv = xr[h];
#pragma unroll
        for (int e = 0; e < NEXP; e++) acc[e] = fmaf(xv, gw[e * HDIM + h], acc[e]);
    }
#pragma unroll
    for (int e = 0; e < NEXP; e++) {
#pragma unroll
        for (int off = 16; off > 0; off >>= 1)
            acc[e] += __shfl_xor_sync(0xffffffffu, acc[e], off);
    }
    if (lane == 0) {
        if (write_logits) {
#pragma unroll
            for (int e = 0; e < NEXP; e++) logits_out[tok * NEXP + e] = acc[e];
        }
        float mx = acc[0];
#pragma unroll
        for (int e = 1; e < NEXP; e++) mx = fmaxf(mx, acc[e]);
        float p[NEXP], s = 0.f;
#pragma unroll
        for (int e = 0; e < NEXP; e++) { p[e] = __expf(acc[e] - mx); s += p[e]; }
        float inv = 1.f / s;
#pragma unroll
        for (int e = 0; e < NEXP; e++) p[e] *= inv;

        int i1 = 0; float m1 = p[0];
#pragma unroll
        for (int e = 1; e < NEXP; e++) if (p[e] > m1) { m1 = p[e]; i1 = e; }
        int i2 = -1; float m2 = -1.f;
#pragma unroll
        for (int e = 0; e < NEXP; e++) {
            if (e == i1) continue;
            if (p[e] > m2) { m2 = p[e]; i2 = e; }
        }
        int pos1 = atomicAdd(&g_cnt[i1], 1);
        g_tok[i1 * T_TOK + pos1] = tok;  g_wt[i1 * T_TOK + pos1] = m1;
        int pos2 = atomicAdd(&g_cnt[i2], 1);
        g_tok[i2 * T_TOK + pos2] = tok;  g_wt[i2 * T_TOK + pos2] = m2;
    }
}

// ---------------- fused pre-pass ------------------------------------------
// grid (1024, 25), block 256.
//  by in [0,8)  : w1 expert by         (K=1024, N=2048)  2 k-tiles/block
//  by in [8,16) : w3 expert by-8
//  by in [16,24): w2 expert by-16      (K=2048, N=1024)
//  by == 24     : x tf32-round+k-perm  16 floats/thread
__global__ void prepass_kernel(const float* __restrict__ x,
                               const float* __restrict__ w1,
                               const float* __restrict__ w3,
                               const float* __restrict__ w2)
{
    const int by = blockIdx.y;
    const int bx = blockIdx.x;
    if (by == 24) {
        int base = (bx * 256 + threadIdx.x) * 16;
#pragma unroll
        for (int q = 0; q < 4; q++) {
            int p = base + q * 4;
            int grp = p & ~15, j = (p >> 2) & 3;
            float4 o;
            o.x = rna_tf32(x[grp + j]);
            o.y = rna_tf32(x[grp + 4 + j]);
            o.z = rna_tf32(x[grp + 8 + j]);
            o.w = rna_tf32(x[grp + 12 + j]);
            *(float4*)(g_xr + p) = o;
        }
        return;
    }

    __shared__ float t[2][32][33];
    const float* in;
    float* out;
    int K, N, n0, k0;
    if (by < 16) {
        K = HDIM; N = FDIM;
        int e = by & 7;
        in  = ((by < 8) ? w1 : w3) + (size_t)e * K * N;
        out = ((by < 8) ? g_w1t : g_w3t) + (size_t)e * K * N;
        n0 = (bx & 63) * 32; k0 = (bx >> 6) * 64;   // 64 n-tiles x 16 k-pairs
    } else {
        K = FDIM; N = HDIM;
        int e = by - 16;
        in  = w2 + (size_t)e * K * N;
        out = g_w2t + (size_t)e * K * N;
        n0 = (bx & 31) * 32; k0 = (bx >> 5) * 64;   // 32 n-tiles x 32 k-pairs
    }

    int kr = threadIdx.x >> 3;            // 0..31
    int nc = (threadIdx.x & 7) * 4;
    // two loads in flight (MLP=2)
    float4 v0 = *(const float4*)(in + (size_t)(k0 + kr) * N + n0 + nc);
    float4 v1 = *(const float4*)(in + (size_t)(k0 + 32 + kr) * N + n0 + nc);
    t[0][kr][nc] = v0.x; t[0][kr][nc + 1] = v0.y; t[0][kr][nc + 2] = v0.z; t[0][kr][nc + 3] = v0.w;
    t[1][kr][nc] = v1.x; t[1][kr][nc + 1] = v1.y; t[1][kr][nc + 2] = v1.z; t[1][kr][nc + 3] = v1.w;
    __syncthreads();

    int nr = threadIdx.x >> 3;            // n within tile
    int c  = threadIdx.x & 7;             // phys 16B chunk
    int g  = (c >> 2) * 16, j = c & 3;    // phys base = g + 4j
#pragma unroll
    for (int q = 0; q < 2; q++) {
        float4 o;
        o.x = rna_tf32(t[q][g + j     ][nr]);
        o.y = rna_tf32(t[q][g + 4 + j ][nr]);
        o.z = rna_tf32(t[q][g + 8 + j ][nr]);
        o.w = rna_tf32(t[q][g + 12 + j][nr]);
        *(float4*)(out + (size_t)(n0 + nr) * K + k0 + q * 32 + g + 4 * j) = o;
    }
}

// =====================================================================
// GEMM13 fused: h = silu(Xg @ W1) * (Xg @ W3)
// BM=128, BN=64, BK=32, 256 thr (8 warps 4m x 2n). Warp: 32r x 32c x 2 mats.
// smem/stage (32KB): A[0,16K) B1[16K,24K) B3[24K,32K). 2 stages, wait0.
// k-loop unrolled x2: stage offsets are LITERALS -> LDS addrs loop-invariant.
// =====================================================================
__global__ void __launch_bounds__(256, 2)
moe_gemm13()
{
    const int e   = blockIdx.z;
    const int cnt = g_cnt[e];
    const int m0  = blockIdx.x * 128;
    if (m0 >= cnt) return;
    const int n0  = blockIdx.y * 64;

    extern __shared__ char dsm[];
    const uint32_t sb = (smem_u32(dsm) + 127u) & ~127u;
    __shared__ const float* s_arow[128];

    const int tid  = threadIdx.x;
    const int warp = tid >> 5;
    const int lane = tid & 31;
    const int qr   = lane >> 2;
    const int qc   = lane & 3;
    const int rq   = warp & 3;
    const int cf   = warp >> 2;

    if (tid < 128) {
        int mm = min(m0 + tid, cnt - 1);
        s_arow[tid] = g_xr + (size_t)g_tok[e * T_TOK + mm] * HDIM;
    }
    __syncthreads();

    const float* b1b = g_w1t + (size_t)e * FDIM * HDIM + (size_t)n0 * HDIM;
    const float* b3b = g_w3t + (size_t)e * FDIM * HDIM + (size_t)n0 * HDIM;

    const int ch  = tid & 7;
    const int rr  = tid >> 3;       // 0..31
    const float* pA[4]; uint32_t dA[4];
#pragma unroll
    for (int i = 0; i < 4; i++) {
        int row = i * 32 + rr;
        pA[i] = s_arow[row] + ch * 4;
        dA[i] = sb + swoff(row, ch);
    }
    const float* pB1[2]; const float* pB3[2]; uint32_t dB[2];
#pragma unroll
    for (int i = 0; i < 2; i++) {
        int row = i * 32 + rr;      // 0..63
        pB1[i] = b1b + (size_t)row * HDIM + ch * 4;
        pB3[i] = b3b + (size_t)row * HDIM + ch * 4;
        dB[i]  = sb + 16384u + swoff(row, ch);
    }

// stage and k-offset are compile-time literals
#define LOAD13(stc_, ko_) do {                                            \
    _Pragma("unroll")                                                     \
    for (int i_ = 0; i_ < 4; i_++)                                        \
        CP_ASYNC16(dA[i_] + (stc_), pA[i_] + (ko_));                      \
    _Pragma("unroll")                                                     \
    for (int i_ = 0; i_ < 2; i_++) {                                      \
        CP_ASYNC16(dB[i_] + (stc_),         pB1[i_] + (ko_));             \
        CP_ASYNC16(dB[i_] + 8192u + (stc_), pB3[i_] + (ko_));             \
    }                                                                     \
    CP_COMMIT();                                                          \
} while (0)

#define COMPUTE13(stc_) do {                                                        \
    _Pragma("unroll")                                                               \
    for (int s = 0; s < 2; s++) {                                                   \
        uint4 alo[2], ahi[2];                                                       \
        _Pragma("unroll")                                                           \
        for (int mt = 0; mt < 2; mt++) {                                            \
            int r = rq * 32 + mt * 16 + qr;                                         \
            lds128(alo[mt], sb + (stc_) + swoff(r,     4 * s + qc));                \
            lds128(ahi[mt], sb + (stc_) + swoff(r + 8, 4 * s + qc));                \
        }                                                                           \
        _Pragma("unroll")                                                           \
        for (int nt = 0; nt < 4; nt++) {                                            \
            int n = cf * 32 + nt * 8 + qr;                                          \
            uint4 b1v, b3v;                                                         \
            lds128(b1v, sb + (stc_) + 16384u + swoff(n, 4 * s + qc));               \
            lds128(b3v, sb + (stc_) + 24576u + swoff(n, 4 * s + qc));               \
            _Pragma("unroll")                                                       \
            for (int mt = 0; mt < 2; mt++) {                                        \
                mma8(acc1[mt][nt], alo[mt].x, ahi[mt].x, alo[mt].y, ahi[mt].y, b1v.x, b1v.y); \
                mma8(acc1[mt][nt], alo[mt].z, ahi[mt].z, alo[mt].w, ahi[mt].w, b1v.z, b1v.w); \
                mma8(acc3[mt][nt], alo[mt].x, ahi[mt].x, alo[mt].y, ahi[mt].y, b3v.x, b3v.y); \
                mma8(acc3[mt][nt], alo[mt].z, ahi[mt].z, alo[mt].w, ahi[mt].w, b3v.z, b3v.w); \
            }                                                                       \
        }                                                                           \
    }                                                                               \
} while (0)

    float acc1[2][4][4], acc3[2][4][4];
#pragma unroll
    for (int mt = 0; mt < 2; mt++)
#pragma unroll
        for (int nt = 0; nt < 4; nt++)
#pragma unroll
            for (int i = 0; i < 4; i++) { acc1[mt][nt][i] = 0.f; acc3[mt][nt][i] = 0.f; }

    LOAD13(0u, 0);
    // advance pointers to k=32
#pragma unroll
    for (int i = 0; i < 4; i++) pA[i] += 32;
    pB1[0] += 32; pB1[1] += 32; pB3[0] += 32; pB3[1] += 32;

    const int NT = HDIM / 32;   // 32 (even)
    for (int t = 0; t < NT; t += 2) {
        CP_WAIT0();
        __syncthreads();
        LOAD13(32768u, 0);            // k=(t+1)*32 into stage 1
        COMPUTE13(0u);
        CP_WAIT0();
        __syncthreads();
        if (t + 2 < NT) LOAD13(0u, 32);   // k=(t+2)*32 into stage 0
        COMPUTE13(32768u);
#pragma unroll
        for (int i = 0; i < 4; i++) pA[i] += 64;
        pB1[0] += 64; pB1[1] += 64; pB3[0] += 64; pB3[1] += 64;
    }

    // epilogue: g_h[m][perm16(f)] = rna(silu(d1)*d3)
#pragma unroll
    for (int mt = 0; mt < 2; mt++) {
#pragma unroll
        for (int h = 0; h < 2; h++) {
            int m = m0 + rq * 32 + mt * 16 + qr + 8 * h;
            if (m >= cnt) continue;
            float* hrow = g_h + ((size_t)e * T_TOK + m) * FDIM;
#pragma unroll
            for (int nt = 0; nt < 4; nt++) {
#pragma unroll
                for (int b = 0; b < 2; b++) {
                    float d1 = acc1[mt][nt][2 * h + b];
                    float d3 = acc3[mt][nt][2 * h + b];
                    float v = rna_tf32(d1 / (1.f + __expf(-d1)) * d3);
                    int f = n0 + cf * 32 + nt * 8 + qc * 2 + b;
                    hrow[perm16(f)] = v;
                }
            }
        }
    }
#undef LOAD13
#undef COMPUTE13
}

// =====================================================================
// GEMM2: y += wt * (h @ W2).  BM=128, BN=128, BK=32, 256 thr (4m x 2n).
// Warp: 32r x 64c. smem/stage (32KB): A[0,16K) B[16K,32K). 2 stages, wait0.
// k-loop unrolled x2 with literal stage offsets.
// =====================================================================
__global__ void __launch_bounds__(256, 2)
moe_gemm2(float* __restrict__ y)
{
    const int e   = blockIdx.z;
    const int cnt = g_cnt[e];
    const int m0  = blockIdx.x * 128;
    if (m0 >= cnt) return;
    const int n0  = blockIdx.y * 128;

    extern __shared__ char dsm[];
    const uint32_t sb = (smem_u32(dsm) + 127u) & ~127u;
    __shared__ const float* s_arow[128];

    const int tid  = threadIdx.x;
    const int warp = tid >> 5;
    const int lane = tid & 31;
    const int qr   = lane >> 2;
    const int qc   = lane & 3;
    const int rq   = warp & 3;
    const int cf   = warp >> 2;

    if (tid < 128) {
        int mm = min(m0 + tid, cnt - 1);
        s_arow[tid] = g_h + ((size_t)e * T_TOK + mm) * FDIM;
    }
    __syncthreads();

    const float* bb = g_w2t + (size_t)e * HDIM * FDIM + (size_t)n0 * FDIM;

    const int ch = tid & 7;
    const int rr = tid >> 3;
    const float* pA[4]; uint32_t dA[4]; const float* pB[4]; uint32_t dB[4];
#pragma unroll
    for (int i = 0; i < 4; i++) {
        int row = i * 32 + rr;
        pA[i] = s_arow[row] + ch * 4;
        dA[i] = sb + swoff(row, ch);
        pB[i] = bb + (size_t)row * FDIM + ch * 4;
        dB[i] = sb + 16384u + swoff(row, ch);
    }

#define LOAD2(stc_, ko_) do {                                             \
    _Pragma("unroll")                                                     \
    for (int i_ = 0; i_ < 4; i_++) {                                      \
        CP_ASYNC16(dA[i_] + (stc_), pA[i_] + (ko_));                      \
        CP_ASYNC16(dB[i_] + (stc_), pB[i_] + (ko_));                      \
    }                                                                     \
    CP_COMMIT();                                                          \
} while (0)

#define COMPUTE2(stc_) do {                                                         \
    _Pragma("unroll")                                                               \
    for (int s = 0; s < 2; s++) {                                                   \
        uint4 alo[2], ahi[2];                                                       \
        _Pragma("unroll")                                                           \
        for (int mt = 0; mt < 2; mt++) {                                            \
            int r = rq * 32 + mt * 16 + qr;                                         \
            lds128(alo[mt], sb + (stc_) + swoff(r,     4 * s + qc));                \
            lds128(ahi[mt], sb + (stc_) + swoff(r + 8, 4 * s + qc));                \
        }                                                                           \
        _Pragma("unroll")                                                           \
        for (int nt = 0; nt < 8; nt++) {                                            \
            int n = cf * 64 + nt * 8 + qr;                                          \
            uint4 bv;                                                               \
            lds128(bv, sb + (stc_) + 16384u + swoff(n, 4 * s + qc));                \
            _Pragma("unroll")                                                       \
            for (int mt = 0; mt < 2; mt++) {                                        \
                mma8(acc[mt][nt], alo[mt].x, ahi[mt].x, alo[mt].y, ahi[mt].y, bv.x, bv.y); \
                mma8(acc[mt][nt], alo[mt].z, ahi[mt].z, alo[mt].w, ahi[mt].w, bv.z, bv.w); \
            }                                                                       \
        }                                                                           \
    }                                                                               \
} while (0)

    float acc[2][8][4];
#pragma unroll
    for (int mt = 0; mt < 2; mt++)
#pragma unroll
        for (int nt = 0; nt < 8; nt++)
#pragma unroll
            for (int i = 0; i < 4; i++) acc[mt][nt][i] = 0.f;

    LOAD2(0u, 0);
#pragma unroll
    for (int i = 0; i < 4; i++) { pA[i] += 32; pB[i] += 32; }

    const int NT = FDIM / 32;   // 64 (even)
    for (int t = 0; t < NT; t += 2) {
        CP_WAIT0();
        __syncthreads();
        LOAD2(32768u, 0);
        COMPUTE2(0u);
        CP_WAIT0();
        __syncthreads();
        if (t + 2 < NT) LOAD2(0u, 32);
        COMPUTE2(32768u);
#pragma unroll
        for (int i = 0; i < 4; i++) { pA[i] += 64; pB[i] += 64; }
    }

    // epilogue: y[tok] += wt * D (REDG atomics - measured cheap)
#pragma unroll
    for (int mt = 0; mt < 2; mt++) {
#pragma unroll
        for (int h = 0; h < 2; h++) {
            int m = m0 + rq * 32 + mt * 16 + qr + 8 * h;
            if (m >= cnt) continue;
            float w   = g_wt [e * T_TOK + m];
            int   tok = g_tok[e * T_TOK + m];
            float* yrow = y + (size_t)tok * HDIM + n0 + cf * 64;
#pragma unroll
            for (int nt = 0; nt < 8; nt++) {
#pragma unroll
                for (int b = 0; b < 2; b++)
                    atomicAdd(yrow + nt * 8 + qc * 2 + b, w * acc[mt][nt][2 * h + b]);
            }
        }
    }
#undef LOAD2
#undef COMPUTE2
}

// ---------------- launch ----------------
extern "C" void kernel_launch(void* const* d_in, const int* in_sizes, int n_in,
                              void* d_out, int out_size)
{
    const float* x  = (const float*)d_in[0];   // [2,2048,1024]
    const float* gw = (const float*)d_in[1];   // [8,1024]
    const float* w1 = (const float*)d_in[2];   // [8,1024,2048]
    const float* w3 = (const float*)d_in[3];   // [8,1024,2048]
    const float* w2 = (const float*)d_in[4];   // [8,2048,1024]
    float* out = (float*)d_out;

    const int SMEM = 2 * 32768 + 128;   // 65664
    cudaFuncSetAttribute(moe_gemm13, cudaFuncAttributeMaxDynamicSharedMemorySize, SMEM);
    cudaFuncSetAttribute(moe_gemm2,  cudaFuncAttributeMaxDynamicSharedMemorySize, SMEM);

    cudaMemsetAsync(out, 0, (size_t)T_TOK * HDIM * sizeof(float));
    init_counts<<<1, 32>>>();

    int write_logits = (out_size >= T_TOK * HDIM + T_TOK * NEXP) ? 1 : 0;
    router_kernel<<<T_TOK / 4, 128>>>(x, gw, out + (size_t)T_TOK * HDIM, write_logits);

    // ONE fused prepass launch (x round + w1/w3/w2 transpose, 2 tiles/block)
    prepass_kernel<<<dim3(1024, 25), 256>>>(x, w1, w3, w2);

    moe_gemm13<<<dim3(T_TOK / 128, FDIM / 64, NEXP), 256, SMEM>>>();
    moe_gemm2 <<<dim3(T_TOK / 128, HDIM / 128, NEXP), 256, SMEM>>>(out);
}